// round 15
// baseline (speedup 1.0000x reference)
#include <cuda_runtime.h>
#include <cuda_fp16.h>

#define NN 100000
#define EE 1600000
#define MAXDEG 128
#define NBIN 129
#define BINSTR 32
#define NEG_SLOPE 0.2f

// ---------------- scratch (static device globals; no allocation) ----------------
__device__ int    g_deg[NN];
__device__ int    g_csr[(size_t)NN * MAXDEG];   // padded CSR: src list per dst
__device__ __half g_featH[(size_t)NN * 32];     // layer-1 features (fp16, 64B rows)
__device__ float  g_el[NN], g_er[NN];
__device__ __half g_feat2H[(size_t)NN * 32];    // layer-2 features (fp16)
__device__ float  g_el2[NN], g_er2[NN];
__device__ int    g_bins[NBIN * BINSTR];        // degree histogram (padded)
__device__ int    g_bincur[NBIN * BINSTR];      // placement cursors (padded)
__device__ int    g_perm[NN];                   // degree-sorted node order

// ---------------- zero degrees + bins ----------------
__global__ void k_zero(int N) {
    int i = blockIdx.x * blockDim.x + threadIdx.x;
    if (i < N) g_deg[i] = 0;
    if (i < NBIN) g_bins[i * BINSTR] = 0;
}

__global__ void k_scatter(const int* __restrict__ src, const int* __restrict__ dst, int E) {
    int i = (blockIdx.x * blockDim.x + threadIdx.x) * 4;
    if (i + 3 < E) {
        int4 s = *(const int4*)(src + i);
        int4 d = *(const int4*)(dst + i);
        int p0 = atomicAdd(&g_deg[d.x], 1);
        int p1 = atomicAdd(&g_deg[d.y], 1);
        int p2 = atomicAdd(&g_deg[d.z], 1);
        int p3 = atomicAdd(&g_deg[d.w], 1);
        if (p0 < MAXDEG) g_csr[(size_t)d.x * MAXDEG + p0] = s.x;
        if (p1 < MAXDEG) g_csr[(size_t)d.y * MAXDEG + p1] = s.y;
        if (p2 < MAXDEG) g_csr[(size_t)d.z * MAXDEG + p2] = s.z;
        if (p3 < MAXDEG) g_csr[(size_t)d.w * MAXDEG + p3] = s.w;
    } else {
        for (; i < E; i++) {
            int d = dst[i];
            int p = atomicAdd(&g_deg[d], 1);
            if (p < MAXDEG) g_csr[(size_t)d * MAXDEG + p] = src[i];
        }
    }
}

// ---------------- degree-binned permutation (counting sort) ----------------
__global__ void k_histbin(int N) {
    __shared__ int sh[NBIN];
    int tid = threadIdx.x;
    if (tid < NBIN) sh[tid] = 0;
    __syncthreads();
    int i = blockIdx.x * blockDim.x + tid;
    if (i < N) {
        int d = g_deg[i]; if (d > MAXDEG) d = MAXDEG;
        atomicAdd(&sh[d], 1);
    }
    __syncthreads();
    if (tid < NBIN && sh[tid]) atomicAdd(&g_bins[tid * BINSTR], sh[tid]);
}

__global__ void k_scanbins() {
    __shared__ int sh[NBIN];
    int t = threadIdx.x;
    if (t < NBIN) sh[t] = g_bins[t * BINSTR];
    __syncthreads();
    if (t == 0) {
        int run = 0;
        for (int k = 0; k < NBIN; k++) { int v = sh[k]; sh[k] = run; run += v; }
    }
    __syncthreads();
    if (t < NBIN) g_bincur[t * BINSTR] = sh[t];
}

__global__ void k_place(int N) {
    int i = blockIdx.x * blockDim.x + threadIdx.x;
    if (i < N) {
        int d = g_deg[i]; if (d > MAXDEG) d = MAXDEG;
        int pos = atomicAdd(&g_bincur[d * BINSTR], 1);
        g_perm[pos] = i;
    }
}

// ---------------- GEMM1 + attention projections (DIN=128) ----------------
__global__ void __launch_bounds__(256) k_gemm_attn1(
        const float* __restrict__ h,
        const float* __restrict__ W,
        const float* __restrict__ al,
        const float* __restrict__ ar,
        int N) {
    constexpr int Q = 32;
    __shared__ float4 Wt4[Q * 32];
    __shared__ float4 hs4[8][4 * Q];
    __shared__ float sal[32], sar[32];

    int tid = threadIdx.x;
    for (int i = tid; i < Q * 32; i += 256) {
        int f = i / Q, q = i - f * Q;
        Wt4[q * 32 + f] = ((const float4*)W)[i];
    }
    if (tid < 32) { sal[tid] = al[tid]; sar[tid] = ar[tid]; }
    __syncthreads();

    int warp = tid >> 5, lane = tid & 31;
    int nbase = blockIdx.x * 32 + warp * 4;
    float4* hw = hs4[warp];

#pragma unroll
    for (int j = 0; j < 4; j++) {
        int n = nbase + j;
        if (n < N) hw[j * Q + lane] = ((const float4*)(h + (size_t)n * 128))[lane];
    }
    __syncwarp();

    float acc[4] = {0.f, 0.f, 0.f, 0.f};
#pragma unroll 4
    for (int q = 0; q < Q; q++) {
        float4 w4 = Wt4[q * 32 + lane];
#pragma unroll
        for (int j = 0; j < 4; j++) {
            float4 h4 = hw[j * Q + q];
            acc[j] = fmaf(w4.x, h4.x, acc[j]);
            acc[j] = fmaf(w4.y, h4.y, acc[j]);
            acc[j] = fmaf(w4.z, h4.z, acc[j]);
            acc[j] = fmaf(w4.w, h4.w, acc[j]);
        }
    }

#pragma unroll
    for (int j = 0; j < 4; j++) {
        int n = nbase + j;
        if (n >= N) break;
        g_featH[(size_t)n * 32 + lane] = __float2half_rn(acc[j]);
        float vl = acc[j] * sal[lane];
        float vr = acc[j] * sar[lane];
#pragma unroll
        for (int o = 16; o; o >>= 1) {
            vl += __shfl_xor_sync(0xffffffffu, vl, o);
            vr += __shfl_xor_sync(0xffffffffu, vr, o);
        }
        if (lane == 0) { g_el[n] = vl; g_er[n] = vr; }
    }
}

// ---- 8-lane-segment-per-node aggregate core (4 nodes/warp) -----------------
__device__ __forceinline__ void edge_loop8(
        const int* __restrict__ csr, int cnt,
        const float* __restrict__ el, const uint4* __restrict__ feat16,
        float ern, unsigned smask, int lane8, int g2, int r4,
        float& ssum, float4& aLo, float4& aHi) {
    for (int j0 = 0; j0 < cnt; j0 += 8) {
        int j = j0 + lane8;
        bool v = j < cnt;
        int s = csr[v ? j : 0];
        float e = el[s] + ern;
        e = (e >= 0.f) ? e : NEG_SLOPE * e;
        float w = v ? __expf(e) : 0.f;
        ssum += w;
        int   sk0 = __shfl_sync(smask, s, 0 + g2, 8);
        float wk0 = __shfl_sync(smask, w, 0 + g2, 8);
        int   sk1 = __shfl_sync(smask, s, 2 + g2, 8);
        float wk1 = __shfl_sync(smask, w, 2 + g2, 8);
        int   sk2 = __shfl_sync(smask, s, 4 + g2, 8);
        float wk2 = __shfl_sync(smask, w, 4 + g2, 8);
        int   sk3 = __shfl_sync(smask, s, 6 + g2, 8);
        float wk3 = __shfl_sync(smask, w, 6 + g2, 8);
        uint4 p0 = feat16[(size_t)sk0 * 4 + r4];
        uint4 p1 = feat16[(size_t)sk1 * 4 + r4];
        uint4 p2 = feat16[(size_t)sk2 * 4 + r4];
        uint4 p3 = feat16[(size_t)sk3 * 4 + r4];
        float2 f;
        f = __half22float2(*(__half2*)&p0.x); aLo.x = fmaf(wk0, f.x, aLo.x); aLo.y = fmaf(wk0, f.y, aLo.y);
        f = __half22float2(*(__half2*)&p0.y); aLo.z = fmaf(wk0, f.x, aLo.z); aLo.w = fmaf(wk0, f.y, aLo.w);
        f = __half22float2(*(__half2*)&p0.z); aHi.x = fmaf(wk0, f.x, aHi.x); aHi.y = fmaf(wk0, f.y, aHi.y);
        f = __half22float2(*(__half2*)&p0.w); aHi.z = fmaf(wk0, f.x, aHi.z); aHi.w = fmaf(wk0, f.y, aHi.w);
        f = __half22float2(*(__half2*)&p1.x); aLo.x = fmaf(wk1, f.x, aLo.x); aLo.y = fmaf(wk1, f.y, aLo.y);
        f = __half22float2(*(__half2*)&p1.y); aLo.z = fmaf(wk1, f.x, aLo.z); aLo.w = fmaf(wk1, f.y, aLo.w);
        f = __half22float2(*(__half2*)&p1.z); aHi.x = fmaf(wk1, f.x, aHi.x); aHi.y = fmaf(wk1, f.y, aHi.y);
        f = __half22float2(*(__half2*)&p1.w); aHi.z = fmaf(wk1, f.x, aHi.z); aHi.w = fmaf(wk1, f.y, aHi.w);
        f = __half22float2(*(__half2*)&p2.x); aLo.x = fmaf(wk2, f.x, aLo.x); aLo.y = fmaf(wk2, f.y, aLo.y);
        f = __half22float2(*(__half2*)&p2.y); aLo.z = fmaf(wk2, f.x, aLo.z); aLo.w = fmaf(wk2, f.y, aLo.w);
        f = __half22float2(*(__half2*)&p2.z); aHi.x = fmaf(wk2, f.x, aHi.x); aHi.y = fmaf(wk2, f.y, aHi.y);
        f = __half22float2(*(__half2*)&p2.w); aHi.z = fmaf(wk2, f.x, aHi.z); aHi.w = fmaf(wk2, f.y, aHi.w);
        f = __half22float2(*(__half2*)&p3.x); aLo.x = fmaf(wk3, f.x, aLo.x); aLo.y = fmaf(wk3, f.y, aLo.y);
        f = __half22float2(*(__half2*)&p3.y); aLo.z = fmaf(wk3, f.x, aLo.z); aLo.w = fmaf(wk3, f.y, aLo.w);
        f = __half22float2(*(__half2*)&p3.z); aHi.x = fmaf(wk3, f.x, aHi.x); aHi.y = fmaf(wk3, f.y, aHi.y);
        f = __half22float2(*(__half2*)&p3.w); aHi.z = fmaf(wk3, f.x, aHi.z); aHi.w = fmaf(wk3, f.y, aHi.w);
    }
#pragma unroll
    for (int o = 4; o; o >>= 1) ssum += __shfl_xor_sync(smask, ssum, o, 8);
    aLo.x += __shfl_xor_sync(smask, aLo.x, 4, 8);
    aLo.y += __shfl_xor_sync(smask, aLo.y, 4, 8);
    aLo.z += __shfl_xor_sync(smask, aLo.z, 4, 8);
    aLo.w += __shfl_xor_sync(smask, aLo.w, 4, 8);
    aHi.x += __shfl_xor_sync(smask, aHi.x, 4, 8);
    aHi.y += __shfl_xor_sync(smask, aHi.y, 4, 8);
    aHi.z += __shfl_xor_sync(smask, aHi.z, 4, 8);
    aHi.w += __shfl_xor_sync(smask, aHi.w, 4, 8);
}

// ---------------- fused: agg1 + GEMM2 + layer-2 projections (perm order) ----
__global__ void __launch_bounds__(256, 6) k_agg1_gemm2(
        const float* __restrict__ b1,
        const float* __restrict__ W2,
        const float* __restrict__ al2,
        const float* __restrict__ ar2,
        int N) {
    __shared__ float4 W2t4[8 * 32];
    __shared__ float sal[32], sar[32];
    __shared__ __align__(16) float rowbuf[32][32];
    __shared__ int nodes[32];

    int tid = threadIdx.x;
    for (int i = tid; i < 8 * 32; i += 256) {
        int f = i / 8, q = i - f * 8;
        W2t4[q * 32 + f] = ((const float4*)W2)[i];
    }
    if (tid < 32) {
        sal[tid] = al2[tid]; sar[tid] = ar2[tid];
        int slot = blockIdx.x * 32 + tid;
        nodes[tid] = (slot < N) ? g_perm[slot] : -1;
    }
    __syncthreads();

    int lane = tid & 31;
    int warp = tid >> 5;
    int quarter = lane >> 3, lane8 = lane & 7;
    int g2 = lane8 >> 2, r4 = lane8 & 3;
    unsigned smask = 0xffu << (quarter << 3);
    int local = warp * 4 + quarter;
    int n = nodes[local];

    int nn = (n >= 0) ? n : 0;
    int cnt = (n >= 0) ? g_deg[nn] : 0;
    if (cnt > MAXDEG) cnt = MAXDEG;

    float ssum = 0.f;
    float4 aLo = {0.f, 0.f, 0.f, 0.f}, aHi = {0.f, 0.f, 0.f, 0.f};
    edge_loop8(g_csr + (size_t)nn * MAXDEG, cnt, g_el,
               (const uint4*)g_featH, g_er[nn],
               smask, lane8, g2, r4, ssum, aLo, aHi);

    if (g2 == 0) {
        float4 bLo = ((const float4*)b1)[2 * r4];
        float4 bHi = ((const float4*)b1)[2 * r4 + 1];
        float inv = (cnt > 0) ? (1.f / ssum) : 0.f;
        float4 oLo, oHi;
        oLo.x = fmaf(aLo.x, inv, bLo.x); oLo.y = fmaf(aLo.y, inv, bLo.y);
        oLo.z = fmaf(aLo.z, inv, bLo.z); oLo.w = fmaf(aLo.w, inv, bLo.w);
        oHi.x = fmaf(aHi.x, inv, bHi.x); oHi.y = fmaf(aHi.y, inv, bHi.y);
        oHi.z = fmaf(aHi.z, inv, bHi.z); oHi.w = fmaf(aHi.w, inv, bHi.w);
        float4* row4 = (float4*)rowbuf[local];
        row4[2 * r4]     = oLo;
        row4[2 * r4 + 1] = oHi;
    }
    __syncwarp();

    // GEMM2 for this warp's 4 nodes (permuted ids): lane = output feature
    float acc[4] = {0.f, 0.f, 0.f, 0.f};
#pragma unroll
    for (int q = 0; q < 8; q++) {
        float4 w4 = W2t4[q * 32 + lane];
#pragma unroll
        for (int j = 0; j < 4; j++) {
            float4 h4 = ((const float4*)rowbuf[warp * 4 + j])[q];
            acc[j] = fmaf(w4.x, h4.x, acc[j]);
            acc[j] = fmaf(w4.y, h4.y, acc[j]);
            acc[j] = fmaf(w4.z, h4.z, acc[j]);
            acc[j] = fmaf(w4.w, h4.w, acc[j]);
        }
    }

#pragma unroll
    for (int j = 0; j < 4; j++) {
        int nj = nodes[warp * 4 + j];
        float vl = acc[j] * sal[lane];
        float vr = acc[j] * sar[lane];
#pragma unroll
        for (int o = 16; o; o >>= 1) {
            vl += __shfl_xor_sync(0xffffffffu, vl, o);
            vr += __shfl_xor_sync(0xffffffffu, vr, o);
        }
        if (nj >= 0) {
            g_feat2H[(size_t)nj * 32 + lane] = __float2half_rn(acc[j]);
            if (lane == 0) { g_el2[nj] = vl; g_er2[nj] = vr; }
        }
    }
}

// ---------------- final aggregate (layer 2, perm order) ----------------
__global__ void __launch_bounds__(256, 6) k_agg2(const float* __restrict__ b2,
                                                 float* __restrict__ out, int N) {
    int tid = threadIdx.x;
    int lane = tid & 31;
    int quarter = lane >> 3, lane8 = lane & 7;
    int g2 = lane8 >> 2, r4 = lane8 & 3;
    unsigned smask = 0xffu << (quarter << 3);
    int slot = ((blockIdx.x * blockDim.x + tid) >> 5) * 4 + quarter;
    int n = (slot < N) ? g_perm[slot] : -1;

    int nn = (n >= 0) ? n : 0;
    int cnt = (n >= 0) ? g_deg[nn] : 0;
    if (cnt > MAXDEG) cnt = MAXDEG;

    float ssum = 0.f;
    float4 aLo = {0.f, 0.f, 0.f, 0.f}, aHi = {0.f, 0.f, 0.f, 0.f};
    edge_loop8(g_csr + (size_t)nn * MAXDEG, cnt, g_el2,
               (const uint4*)g_feat2H, g_er2[nn],
               smask, lane8, g2, r4, ssum, aLo, aHi);

    if (n >= 0 && g2 == 0) {
        float4 bLo = ((const float4*)b2)[2 * r4];
        float4 bHi = ((const float4*)b2)[2 * r4 + 1];
        float inv = (cnt > 0) ? (1.f / ssum) : 0.f;
        float4 oLo, oHi;
        oLo.x = fmaf(aLo.x, inv, bLo.x); oLo.y = fmaf(aLo.y, inv, bLo.y);
        oLo.z = fmaf(aLo.z, inv, bLo.z); oLo.w = fmaf(aLo.w, inv, bLo.w);
        oHi.x = fmaf(aHi.x, inv, bHi.x); oHi.y = fmaf(aHi.y, inv, bHi.y);
        oHi.z = fmaf(aHi.z, inv, bHi.z); oHi.w = fmaf(aHi.w, inv, bHi.w);
        float4* out4 = (float4*)out;
        out4[(size_t)n * 8 + 2 * r4]     = oLo;
        out4[(size_t)n * 8 + 2 * r4 + 1] = oHi;
    }
}

// ---------------- driver ----------------
extern "C" void kernel_launch(void* const* d_in, const int* in_sizes, int n_in,
                              void* d_out, int out_size) {
    const float* features = (const float*)d_in[0];
    const int*   src      = (const int*)d_in[1];
    const int*   dst      = (const int*)d_in[2];
    const float* W1  = (const float*)d_in[3];
    const float* al1 = (const float*)d_in[4];
    const float* ar1 = (const float*)d_in[5];
    const float* b1  = (const float*)d_in[6];
    const float* W2  = (const float*)d_in[7];
    const float* al2 = (const float*)d_in[8];
    const float* ar2 = (const float*)d_in[9];
    const float* b2  = (const float*)d_in[10];

    int E = in_sizes[1];
    int N = in_sizes[0] / 128;
    if (N > NN) N = NN;
    if (E > EE) E = EE;

    float* out = (float*)d_out;

    static cudaStream_t s_side = nullptr;
    static cudaEvent_t ev_fork = nullptr, ev_join = nullptr;
    if (!s_side) {
        cudaStreamCreateWithFlags(&s_side, cudaStreamNonBlocking);
        cudaEventCreateWithFlags(&ev_fork, cudaEventDisableTiming);
        cudaEventCreateWithFlags(&ev_join, cudaEventDisableTiming);
    }

    const int T = 256;
    int gN = (N + T - 1) / T;
    int gE4 = (E / 4 + T) / T + 1;
    int g32 = (N + 31) / 32;       // 8 warps x 4 nodes per 256-thread block

    // fork: GEMM1 runs concurrently with CSR build + degree sort
    cudaEventRecord(ev_fork, 0);
    cudaStreamWaitEvent(s_side, ev_fork, 0);
    k_gemm_attn1<<<g32, T, 0, s_side>>>(features, W1, al1, ar1, N);
    cudaEventRecord(ev_join, s_side);

    k_zero<<<gN, T>>>(N);
    k_scatter<<<gE4, T>>>(src, dst, E);
    k_histbin<<<gN, T>>>(N);
    k_scanbins<<<1, 256>>>();
    k_place<<<gN, T>>>(N);

    cudaStreamWaitEvent(0, ev_join, 0);

    // layer-1 aggregate + fused GEMM2 + layer-2 projections (degree-binned)
    k_agg1_gemm2<<<g32, T>>>(b1, W2, al2, ar2, N);
    // layer-2 aggregate -> final output (degree-binned)
    k_agg2<<<g32, T>>>(b2, out, N);
}

// round 17
// speedup vs baseline: 1.2100x; 1.2100x over previous
#include <cuda_runtime.h>
#include <cuda_fp16.h>

#define NN 100000
#define EE 1600000
#define MAXDEG 128
#define NEG_SLOPE 0.2f

// ---------------- scratch (static device globals; no allocation) ----------------
__device__ int    g_deg[NN];
__device__ int    g_csr[(size_t)NN * MAXDEG];   // padded CSR: src list per dst
__device__ __half g_featH[(size_t)NN * 32];     // layer-1 features (fp16, 64B rows)
__device__ float  g_el[NN], g_er[NN];
__device__ __half g_feat2H[(size_t)NN * 32];    // layer-2 features (fp16)
__device__ float  g_el2[NN], g_er2[NN];

// ---------------- build: zero degrees, then direct scatter ----------------
__global__ void k_zero(int N) {
    int i = blockIdx.x * blockDim.x + threadIdx.x;
    if (i < N) g_deg[i] = 0;
}

__global__ void k_scatter(const int* __restrict__ src, const int* __restrict__ dst, int E) {
    int i = (blockIdx.x * blockDim.x + threadIdx.x) * 4;
    if (i + 3 < E) {
        int4 s = *(const int4*)(src + i);
        int4 d = *(const int4*)(dst + i);
        int p0 = atomicAdd(&g_deg[d.x], 1);
        int p1 = atomicAdd(&g_deg[d.y], 1);
        int p2 = atomicAdd(&g_deg[d.z], 1);
        int p3 = atomicAdd(&g_deg[d.w], 1);
        if (p0 < MAXDEG) g_csr[(size_t)d.x * MAXDEG + p0] = s.x;
        if (p1 < MAXDEG) g_csr[(size_t)d.y * MAXDEG + p1] = s.y;
        if (p2 < MAXDEG) g_csr[(size_t)d.z * MAXDEG + p2] = s.z;
        if (p3 < MAXDEG) g_csr[(size_t)d.w * MAXDEG + p3] = s.w;
    } else {
        for (; i < E; i++) {
            int d = dst[i];
            int p = atomicAdd(&g_deg[d], 1);
            if (p < MAXDEG) g_csr[(size_t)d * MAXDEG + p] = src[i];
        }
    }
}

// ---------------- GEMM1 + attention projections (DIN=128) ----------------
__global__ void __launch_bounds__(256) k_gemm_attn1(
        const float* __restrict__ h,
        const float* __restrict__ W,
        const float* __restrict__ al,
        const float* __restrict__ ar,
        int N) {
    constexpr int Q = 32;
    __shared__ float4 Wt4[Q * 32];
    __shared__ float4 hs4[8][4 * Q];
    __shared__ float sal[32], sar[32];

    int tid = threadIdx.x;
    for (int i = tid; i < Q * 32; i += 256) {
        int f = i / Q, q = i - f * Q;
        Wt4[q * 32 + f] = ((const float4*)W)[i];
    }
    if (tid < 32) { sal[tid] = al[tid]; sar[tid] = ar[tid]; }
    __syncthreads();

    int warp = tid >> 5, lane = tid & 31;
    int nbase = blockIdx.x * 32 + warp * 4;
    float4* hw = hs4[warp];

#pragma unroll
    for (int j = 0; j < 4; j++) {
        int n = nbase + j;
        if (n < N) hw[j * Q + lane] = ((const float4*)(h + (size_t)n * 128))[lane];
    }
    __syncwarp();

    float acc[4] = {0.f, 0.f, 0.f, 0.f};
#pragma unroll 4
    for (int q = 0; q < Q; q++) {
        float4 w4 = Wt4[q * 32 + lane];
#pragma unroll
        for (int j = 0; j < 4; j++) {
            float4 h4 = hw[j * Q + q];
            acc[j] = fmaf(w4.x, h4.x, acc[j]);
            acc[j] = fmaf(w4.y, h4.y, acc[j]);
            acc[j] = fmaf(w4.z, h4.z, acc[j]);
            acc[j] = fmaf(w4.w, h4.w, acc[j]);
        }
    }

#pragma unroll
    for (int j = 0; j < 4; j++) {
        int n = nbase + j;
        if (n >= N) break;
        g_featH[(size_t)n * 32 + lane] = __float2half_rn(acc[j]);
        float vl = acc[j] * sal[lane];
        float vr = acc[j] * sar[lane];
#pragma unroll
        for (int o = 16; o; o >>= 1) {
            vl += __shfl_xor_sync(0xffffffffu, vl, o);
            vr += __shfl_xor_sync(0xffffffffu, vr, o);
        }
        if (lane == 0) { g_el[n] = vl; g_er[n] = vr; }
    }
}

// ---- 8-lane-segment-per-node aggregate core (4 nodes/warp) -----------------
// Segment-masked shuffles (segments diverge on trip count).
__device__ __forceinline__ void edge_loop8(
        const int* __restrict__ csr, int cnt,
        const float* __restrict__ el, const uint4* __restrict__ feat16,
        float ern, unsigned smask, int lane8, int g2, int r4,
        float& ssum, float4& aLo, float4& aHi) {
    for (int j0 = 0; j0 < cnt; j0 += 8) {
        int j = j0 + lane8;
        bool v = j < cnt;
        int s = csr[v ? j : 0];
        float e = el[s] + ern;
        e = (e >= 0.f) ? e : NEG_SLOPE * e;
        float w = v ? __expf(e) : 0.f;
        ssum += w;
        int   sk0 = __shfl_sync(smask, s, 0 + g2, 8);
        float wk0 = __shfl_sync(smask, w, 0 + g2, 8);
        int   sk1 = __shfl_sync(smask, s, 2 + g2, 8);
        float wk1 = __shfl_sync(smask, w, 2 + g2, 8);
        int   sk2 = __shfl_sync(smask, s, 4 + g2, 8);
        float wk2 = __shfl_sync(smask, w, 4 + g2, 8);
        int   sk3 = __shfl_sync(smask, s, 6 + g2, 8);
        float wk3 = __shfl_sync(smask, w, 6 + g2, 8);
        uint4 p0 = feat16[(size_t)sk0 * 4 + r4];
        uint4 p1 = feat16[(size_t)sk1 * 4 + r4];
        uint4 p2 = feat16[(size_t)sk2 * 4 + r4];
        uint4 p3 = feat16[(size_t)sk3 * 4 + r4];
        float2 f;
        f = __half22float2(*(__half2*)&p0.x); aLo.x = fmaf(wk0, f.x, aLo.x); aLo.y = fmaf(wk0, f.y, aLo.y);
        f = __half22float2(*(__half2*)&p0.y); aLo.z = fmaf(wk0, f.x, aLo.z); aLo.w = fmaf(wk0, f.y, aLo.w);
        f = __half22float2(*(__half2*)&p0.z); aHi.x = fmaf(wk0, f.x, aHi.x); aHi.y = fmaf(wk0, f.y, aHi.y);
        f = __half22float2(*(__half2*)&p0.w); aHi.z = fmaf(wk0, f.x, aHi.z); aHi.w = fmaf(wk0, f.y, aHi.w);
        f = __half22float2(*(__half2*)&p1.x); aLo.x = fmaf(wk1, f.x, aLo.x); aLo.y = fmaf(wk1, f.y, aLo.y);
        f = __half22float2(*(__half2*)&p1.y); aLo.z = fmaf(wk1, f.x, aLo.z); aLo.w = fmaf(wk1, f.y, aLo.w);
        f = __half22float2(*(__half2*)&p1.z); aHi.x = fmaf(wk1, f.x, aHi.x); aHi.y = fmaf(wk1, f.y, aHi.y);
        f = __half22float2(*(__half2*)&p1.w); aHi.z = fmaf(wk1, f.x, aHi.z); aHi.w = fmaf(wk1, f.y, aHi.w);
        f = __half22float2(*(__half2*)&p2.x); aLo.x = fmaf(wk2, f.x, aLo.x); aLo.y = fmaf(wk2, f.y, aLo.y);
        f = __half22float2(*(__half2*)&p2.y); aLo.z = fmaf(wk2, f.x, aLo.z); aLo.w = fmaf(wk2, f.y, aLo.w);
        f = __half22float2(*(__half2*)&p2.z); aHi.x = fmaf(wk2, f.x, aHi.x); aHi.y = fmaf(wk2, f.y, aHi.y);
        f = __half22float2(*(__half2*)&p2.w); aHi.z = fmaf(wk2, f.x, aHi.z); aHi.w = fmaf(wk2, f.y, aHi.w);
        f = __half22float2(*(__half2*)&p3.x); aLo.x = fmaf(wk3, f.x, aLo.x); aLo.y = fmaf(wk3, f.y, aLo.y);
        f = __half22float2(*(__half2*)&p3.y); aLo.z = fmaf(wk3, f.x, aLo.z); aLo.w = fmaf(wk3, f.y, aLo.w);
        f = __half22float2(*(__half2*)&p3.z); aHi.x = fmaf(wk3, f.x, aHi.x); aHi.y = fmaf(wk3, f.y, aHi.y);
        f = __half22float2(*(__half2*)&p3.w); aHi.z = fmaf(wk3, f.x, aHi.z); aHi.w = fmaf(wk3, f.y, aHi.w);
    }
#pragma unroll
    for (int o = 4; o; o >>= 1) ssum += __shfl_xor_sync(smask, ssum, o, 8);
    aLo.x += __shfl_xor_sync(smask, aLo.x, 4, 8);
    aLo.y += __shfl_xor_sync(smask, aLo.y, 4, 8);
    aLo.z += __shfl_xor_sync(smask, aLo.z, 4, 8);
    aLo.w += __shfl_xor_sync(smask, aLo.w, 4, 8);
    aHi.x += __shfl_xor_sync(smask, aHi.x, 4, 8);
    aHi.y += __shfl_xor_sync(smask, aHi.y, 4, 8);
    aHi.z += __shfl_xor_sync(smask, aHi.z, 4, 8);
    aHi.w += __shfl_xor_sync(smask, aHi.w, 4, 8);
}

// ---------------- fused: agg1 (4 nodes/warp) + GEMM2 + layer-2 projections --
__global__ void __launch_bounds__(256, 6) k_agg1_gemm2(
        const float* __restrict__ b1,
        const float* __restrict__ W2,
        const float* __restrict__ al2,
        const float* __restrict__ ar2,
        int N) {
    __shared__ float4 W2t4[8 * 32];          // W2t4[q*32+f] = W2[f][4q..4q+3]
    __shared__ float sal[32], sar[32];
    __shared__ __align__(16) float rowbuf[32][32];   // [local node][feature]

    int tid = threadIdx.x;
    for (int i = tid; i < 8 * 32; i += 256) {
        int f = i / 8, q = i - f * 8;
        W2t4[q * 32 + f] = ((const float4*)W2)[i];
    }
    if (tid < 32) { sal[tid] = al2[tid]; sar[tid] = ar2[tid]; }
    __syncthreads();

    int lane = tid & 31;
    int warp = tid >> 5;
    int quarter = lane >> 3, lane8 = lane & 7;
    int g2 = lane8 >> 2, r4 = lane8 & 3;
    unsigned smask = 0xffu << (quarter << 3);
    int local = warp * 4 + quarter;
    int n = blockIdx.x * 32 + local;

    int nn = (n < N) ? n : (N - 1);
    int cnt = (n < N) ? g_deg[nn] : 0;
    if (cnt > MAXDEG) cnt = MAXDEG;

    float ssum = 0.f;
    float4 aLo = {0.f, 0.f, 0.f, 0.f}, aHi = {0.f, 0.f, 0.f, 0.f};
    edge_loop8(g_csr + (size_t)nn * MAXDEG, cnt, g_el,
               (const uint4*)g_featH, g_er[nn],
               smask, lane8, g2, r4, ssum, aLo, aHi);

    // layer-1 row -> shared (g2==0 lanes hold the reduced values)
    if (g2 == 0) {
        float4 bLo = ((const float4*)b1)[2 * r4];
        float4 bHi = ((const float4*)b1)[2 * r4 + 1];
        float inv = (cnt > 0) ? (1.f / ssum) : 0.f;
        float4 oLo, oHi;
        oLo.x = fmaf(aLo.x, inv, bLo.x); oLo.y = fmaf(aLo.y, inv, bLo.y);
        oLo.z = fmaf(aLo.z, inv, bLo.z); oLo.w = fmaf(aLo.w, inv, bLo.w);
        oHi.x = fmaf(aHi.x, inv, bHi.x); oHi.y = fmaf(aHi.y, inv, bHi.y);
        oHi.z = fmaf(aHi.z, inv, bHi.z); oHi.w = fmaf(aHi.w, inv, bHi.w);
        float4* row4 = (float4*)rowbuf[local];
        row4[2 * r4]     = oLo;
        row4[2 * r4 + 1] = oHi;
    }
    __syncwarp();   // warp's 4 segments wrote the warp's 4 rows

    // GEMM2 for this warp's 4 nodes: lane = output feature
    int nbase = blockIdx.x * 32 + warp * 4;
    float acc[4] = {0.f, 0.f, 0.f, 0.f};
#pragma unroll
    for (int q = 0; q < 8; q++) {
        float4 w4 = W2t4[q * 32 + lane];
#pragma unroll
        for (int j = 0; j < 4; j++) {
            float4 h4 = ((const float4*)rowbuf[warp * 4 + j])[q];
            acc[j] = fmaf(w4.x, h4.x, acc[j]);
            acc[j] = fmaf(w4.y, h4.y, acc[j]);
            acc[j] = fmaf(w4.z, h4.z, acc[j]);
            acc[j] = fmaf(w4.w, h4.w, acc[j]);
        }
    }

#pragma unroll
    for (int j = 0; j < 4; j++) {
        int nj = nbase + j;
        if (nj >= N) break;
        g_feat2H[(size_t)nj * 32 + lane] = __float2half_rn(acc[j]);
        float vl = acc[j] * sal[lane];
        float vr = acc[j] * sar[lane];
#pragma unroll
        for (int o = 16; o; o >>= 1) {
            vl += __shfl_xor_sync(0xffffffffu, vl, o);
            vr += __shfl_xor_sync(0xffffffffu, vr, o);
        }
        if (lane == 0) { g_el2[nj] = vl; g_er2[nj] = vr; }
    }
}

// ---------------- final aggregate (layer 2) ----------------
__global__ void __launch_bounds__(256, 6) k_agg2(const float* __restrict__ b2,
                                                 float* __restrict__ out, int N) {
    int tid = threadIdx.x;
    int lane = tid & 31;
    int quarter = lane >> 3, lane8 = lane & 7;
    int g2 = lane8 >> 2, r4 = lane8 & 3;
    unsigned smask = 0xffu << (quarter << 3);
    int n = ((blockIdx.x * blockDim.x + tid) >> 5) * 4 + quarter;

    int nn = (n < N) ? n : (N - 1);
    int cnt = (n < N) ? g_deg[nn] : 0;
    if (cnt > MAXDEG) cnt = MAXDEG;

    float ssum = 0.f;
    float4 aLo = {0.f, 0.f, 0.f, 0.f}, aHi = {0.f, 0.f, 0.f, 0.f};
    edge_loop8(g_csr + (size_t)nn * MAXDEG, cnt, g_el2,
               (const uint4*)g_feat2H, g_er2[nn],
               smask, lane8, g2, r4, ssum, aLo, aHi);

    if (n < N && g2 == 0) {
        float4 bLo = ((const float4*)b2)[2 * r4];
        float4 bHi = ((const float4*)b2)[2 * r4 + 1];
        float inv = (cnt > 0) ? (1.f / ssum) : 0.f;
        float4 oLo, oHi;
        oLo.x = fmaf(aLo.x, inv, bLo.x); oLo.y = fmaf(aLo.y, inv, bLo.y);
        oLo.z = fmaf(aLo.z, inv, bLo.z); oLo.w = fmaf(aLo.w, inv, bLo.w);
        oHi.x = fmaf(aHi.x, inv, bHi.x); oHi.y = fmaf(aHi.y, inv, bHi.y);
        oHi.z = fmaf(aHi.z, inv, bHi.z); oHi.w = fmaf(aHi.w, inv, bHi.w);
        float4* out4 = (float4*)out;
        out4[(size_t)n * 8 + 2 * r4]     = oLo;
        out4[(size_t)n * 8 + 2 * r4 + 1] = oHi;
    }
}

// ---------------- driver ----------------
extern "C" void kernel_launch(void* const* d_in, const int* in_sizes, int n_in,
                              void* d_out, int out_size) {
    const float* features = (const float*)d_in[0];
    const int*   src      = (const int*)d_in[1];
    const int*   dst      = (const int*)d_in[2];
    const float* W1  = (const float*)d_in[3];
    const float* al1 = (const float*)d_in[4];
    const float* ar1 = (const float*)d_in[5];
    const float* b1  = (const float*)d_in[6];
    const float* W2  = (const float*)d_in[7];
    const float* al2 = (const float*)d_in[8];
    const float* ar2 = (const float*)d_in[9];
    const float* b2  = (const float*)d_in[10];

    int E = in_sizes[1];
    int N = in_sizes[0] / 128;
    if (N > NN) N = NN;
    if (E > EE) E = EE;

    float* out = (float*)d_out;

    static cudaStream_t s_side = nullptr;
    static cudaEvent_t ev_fork = nullptr, ev_join = nullptr;
    if (!s_side) {
        cudaStreamCreateWithFlags(&s_side, cudaStreamNonBlocking);
        cudaEventCreateWithFlags(&ev_fork, cudaEventDisableTiming);
        cudaEventCreateWithFlags(&ev_join, cudaEventDisableTiming);
    }

    const int T = 256;
    int gN = (N + T - 1) / T;
    int gE4 = (E / 4 + T) / T + 1;
    int g32 = (N + 31) / 32;       // 8 warps x 4 nodes per 256-thread block

    // fork: GEMM1 runs concurrently with CSR build
    cudaEventRecord(ev_fork, 0);
    cudaStreamWaitEvent(s_side, ev_fork, 0);
    k_gemm_attn1<<<g32, T, 0, s_side>>>(features, W1, al1, ar1, N);
    cudaEventRecord(ev_join, s_side);

    k_zero<<<gN, T>>>(N);
    k_scatter<<<gE4, T>>>(src, dst, E);

    cudaStreamWaitEvent(0, ev_join, 0);

    // layer-1 aggregate + fused GEMM2 + layer-2 projections
    k_agg1_gemm2<<<g32, T>>>(b1, W2, al2, ar2, N);
    // layer-2 aggregate -> final output
    k_agg2<<<g32, T>>>(b2, out, N);
}